// round 1
// baseline (speedup 1.0000x reference)
#include <cuda_runtime.h>
#include <cuda_bf16.h>
#include <math.h>

#define Bc 4
#define Sc 2048
#define Ec 512
#define Hc 8
#define Dc 64
#define HDc 512
#define Mc (Bc*Sc)          // 8192

// ---------------- scratch (static device globals; no allocation) ----------------
__device__ float g_q[Bc*Hc*Sc*Dc];   // [B,H,S,D]
__device__ float g_k[Bc*Hc*Sc*Dc];
__device__ float g_v[Bc*Hc*Sc*Dc];
__device__ float g_o[Mc*HDc];        // [B*S, H*D]
__device__ unsigned char g_pad[Mc];  // B*S
__device__ int g_is_i32;

// ---------------- pad dtype detection (int32 vs int64) ----------------
// If padding_pos is int64 (little-endian, values 0/1), every odd 32-bit word of
// the first 8192 words is the zero high-half. If it's int32, the odd words are
// random 0/1 (all-zero has prob 2^-4096). Reading only the first 8192 words is
// in-bounds for both layouts.
__global__ void detect_pad_kernel(const unsigned int* __restrict__ p) {
    __shared__ unsigned int red[256];
    unsigned int acc = 0;
    for (int i = threadIdx.x; i < Mc; i += 256)
        if (i & 1) acc |= p[i];
    red[threadIdx.x] = acc;
    __syncthreads();
    for (int s = 128; s > 0; s >>= 1) {
        if (threadIdx.x < s) red[threadIdx.x] |= red[threadIdx.x + s];
        __syncthreads();
    }
    if (threadIdx.x == 0) g_is_i32 = (red[0] != 0u) ? 1 : 0;
}

__global__ void extract_pad_kernel(const int* __restrict__ p) {
    int i = blockIdx.x * 256 + threadIdx.x;   // grid covers 8192
    int is32 = g_is_i32;
    int v = is32 ? p[i] : p[2 * i];           // int64 low word holds the value
    g_pad[i] = (unsigned char)(v != 0);
}

// ---------------- fused QKV projection GEMM ----------------
// C[m,n] = x[m,:] @ W[:,n] + bias[n], stored permuted into [B,H,S,D].
// 64x64 tile, K-tile 32, 256 threads, 4x4 micro-tile per thread.
__global__ __launch_bounds__(256) void qkv_gemm_kernel(
    const float* __restrict__ x,
    const float* __restrict__ Wq, const float* __restrict__ bq,
    const float* __restrict__ Wk, const float* __restrict__ bk,
    const float* __restrict__ Wv, const float* __restrict__ bv)
{
    __shared__ float As[32][68];   // x tile, transposed [k][m]
    __shared__ float Bs[32][68];   // W tile [k][n]
    int t = threadIdx.x;
    int which = blockIdx.x >> 3;       // 0=q 1=k 2=v
    int nt = blockIdx.x & 7;
    int mBase = blockIdx.y * 64;
    int n0 = nt * 64;

    const float* W    = (which == 0) ? Wq : ((which == 1) ? Wk : Wv);
    const float* bias = (which == 0) ? bq : ((which == 1) ? bk : bv);
    float* dst        = (which == 0) ? g_q : ((which == 1) ? g_k : g_v);

    int tx = t & 15, ty = t >> 4;
    int r0 = ty * 4, c0 = tx * 4;
    float acc[4][4] = {};

    for (int k0 = 0; k0 < Ec; k0 += 32) {
        #pragma unroll
        for (int i = 0; i < 8; i++) {
            int idx = i * 256 + t;
            int m = idx >> 5, k = idx & 31;
            As[k][m] = x[(size_t)(mBase + m) * Ec + k0 + k];
        }
        #pragma unroll
        for (int i = 0; i < 8; i++) {
            int idx = i * 256 + t;
            int n = idx & 63, k = idx >> 6;
            Bs[k][n] = W[(size_t)(k0 + k) * HDc + n0 + n];
        }
        __syncthreads();
        #pragma unroll
        for (int kk = 0; kk < 32; kk++) {
            float4 a = *(const float4*)&As[kk][r0];
            float4 b = *(const float4*)&Bs[kk][c0];
            float av[4] = {a.x, a.y, a.z, a.w};
            float bw[4] = {b.x, b.y, b.z, b.w};
            #pragma unroll
            for (int i = 0; i < 4; i++)
                #pragma unroll
                for (int j = 0; j < 4; j++)
                    acc[i][j] += av[i] * bw[j];
        }
        __syncthreads();
    }

    #pragma unroll
    for (int i = 0; i < 4; i++) {
        int m = mBase + r0 + i;
        int bb = m >> 11;           // /S
        int s  = m & (Sc - 1);
        #pragma unroll
        for (int j = 0; j < 4; j++) {
            int n = n0 + c0 + j;
            int h = n >> 6;         // /D
            int d = n & (Dc - 1);
            dst[(((size_t)(bb * Hc + h)) * Sc + s) * Dc + d] = acc[i][j] + bias[n];
        }
    }
}

// ---------------- flash attention (fp32, online softmax) ----------------
// grid: (S/64 q-tiles, B*H). 256 threads, 4x4 micro-tiles, 64x64 key tiles.
#define ATTN_SMEM_FLOATS (4*64*68 + 5*64)
__global__ __launch_bounds__(256) void attn_kernel()
{
    extern __shared__ float sm[];
    float* QsT  = sm;                // [d][q] 64x68, pre-scaled by 1/8
    float* KsT  = sm + 64*68;        // [d][k]
    float* Vs   = sm + 2*64*68;      // [k][d]
    float* Ss   = sm + 3*64*68;      // [q][k] scores -> probs
    float* smM  = sm + 4*64*68;      // 64 running max
    float* smL  = smM + 64;          // 64 running sum
    float* smR  = smL + 64;          // 64 rescale
    float* padQ = smR + 64;          // 64
    float* padK = padQ + 64;         // 64

    int t  = threadIdx.x;
    int qt = blockIdx.x;
    int bh = blockIdx.y;
    int bb = bh >> 3;                // /H
    int qBase = qt * 64;

    const float* Qg = g_q + (size_t)bh * Sc * Dc;
    const float* Kg = g_k + (size_t)bh * Sc * Dc;
    const float* Vg = g_v + (size_t)bh * Sc * Dc;

    // Load Q tile transposed, fold in 1/sqrt(D)=0.125
    #pragma unroll
    for (int i = 0; i < 16; i++) {
        int idx = i * 256 + t;
        int row = idx >> 6, d = idx & 63;
        QsT[d * 68 + row] = Qg[(size_t)(qBase + row) * Dc + d] * 0.125f;
    }
    if (t < 64) {
        padQ[t] = (float)g_pad[bb * Sc + qBase + t];
        smM[t]  = -3.0e38f;
        smL[t]  = 0.0f;
    }
    int tx = t & 15, ty = t >> 4;
    int r0 = ty * 4, c0 = tx * 4;
    float acc[4][4] = {};
    __syncthreads();

    for (int kt = 0; kt < Sc; kt += 64) {
        // load K (transposed) and V tiles
        #pragma unroll
        for (int i = 0; i < 16; i++) {
            int idx = i * 256 + t;
            int row = idx >> 6, d = idx & 63;
            float kvv = Kg[(size_t)(kt + row) * Dc + d];
            float vvv = Vg[(size_t)(kt + row) * Dc + d];
            KsT[d * 68 + row] = kvv;
            Vs[row * 68 + d]  = vvv;
        }
        if (t < 64) padK[t] = (float)g_pad[bb * Sc + kt + t];
        __syncthreads();

        // S = (Q/8) K^T, masked
        float s4[4][4] = {};
        #pragma unroll 16
        for (int d = 0; d < 64; d++) {
            float4 a = *(const float4*)&QsT[d * 68 + r0];
            float4 b = *(const float4*)&KsT[d * 68 + c0];
            float av[4] = {a.x, a.y, a.z, a.w};
            float bw[4] = {b.x, b.y, b.z, b.w};
            #pragma unroll
            for (int i = 0; i < 4; i++)
                #pragma unroll
                for (int j = 0; j < 4; j++)
                    s4[i][j] += av[i] * bw[j];
        }
        #pragma unroll
        for (int i = 0; i < 4; i++) {
            float pq = padQ[r0 + i];
            #pragma unroll
            for (int j = 0; j < 4; j++) {
                float vv = (pq + padK[c0 + j] > 0.0f) ? -1e13f : s4[i][j];
                Ss[(r0 + i) * 68 + c0 + j] = vv;
            }
        }
        __syncthreads();

        // online softmax: 4 threads per row (lanes aligned in groups of 4)
        {
            int row = t >> 2, part = t & 3;
            float* srow = &Ss[row * 68 + part * 16];
            float mx = -3.0e38f;
            #pragma unroll
            for (int j = 0; j < 16; j++) mx = fmaxf(mx, srow[j]);
            mx = fmaxf(mx, __shfl_xor_sync(0xffffffffu, mx, 1));
            mx = fmaxf(mx, __shfl_xor_sync(0xffffffffu, mx, 2));
            float mOld = smM[row];
            float mNew = fmaxf(mOld, mx);
            float sum = 0.0f;
            #pragma unroll
            for (int j = 0; j < 16; j++) {
                float p = __expf(srow[j] - mNew);
                srow[j] = p;
                sum += p;
            }
            sum += __shfl_xor_sync(0xffffffffu, sum, 1);
            sum += __shfl_xor_sync(0xffffffffu, sum, 2);
            if (part == 0) {
                float scale = __expf(mOld - mNew);
                smL[row] = smL[row] * scale + sum;
                smM[row] = mNew;
                smR[row] = scale;
            }
        }
        __syncthreads();

        // rescale accumulators, then O += P @ V
        float rs[4];
        #pragma unroll
        for (int i = 0; i < 4; i++) rs[i] = smR[r0 + i];
        #pragma unroll
        for (int i = 0; i < 4; i++)
            #pragma unroll
            for (int j = 0; j < 4; j++)
                acc[i][j] *= rs[i];

        #pragma unroll 8
        for (int kk = 0; kk < 64; kk++) {
            float4 b = *(const float4*)&Vs[kk * 68 + c0];
            #pragma unroll
            for (int i = 0; i < 4; i++) {
                float a = Ss[(r0 + i) * 68 + kk];
                acc[i][0] += a * b.x;
                acc[i][1] += a * b.y;
                acc[i][2] += a * b.z;
                acc[i][3] += a * b.w;
            }
        }
        __syncthreads();
    }

    // epilogue: normalize by l, store to [B*S, H*D]
    int h = bh & 7;
    #pragma unroll
    for (int i = 0; i < 4; i++) {
        float inv = 1.0f / smL[r0 + i];
        int q = qBase + r0 + i;
        float* dstp = &g_o[((size_t)(bb * Sc + q)) * HDc + h * Dc];
        #pragma unroll
        for (int j = 0; j < 4; j++)
            dstp[c0 + j] = acc[i][j] * inv;
    }
}

// ---------------- output projection GEMM ----------------
__global__ __launch_bounds__(256) void out_gemm_kernel(
    const float* __restrict__ Wo, const float* __restrict__ bo,
    float* __restrict__ out)
{
    __shared__ float As[32][68];
    __shared__ float Bs[32][68];
    int t = threadIdx.x;
    int nt = blockIdx.x;
    int mBase = blockIdx.y * 64;
    int n0 = nt * 64;
    int tx = t & 15, ty = t >> 4;
    int r0 = ty * 4, c0 = tx * 4;
    float acc[4][4] = {};

    for (int k0 = 0; k0 < HDc; k0 += 32) {
        #pragma unroll
        for (int i = 0; i < 8; i++) {
            int idx = i * 256 + t;
            int m = idx >> 5, k = idx & 31;
            As[k][m] = g_o[(size_t)(mBase + m) * HDc + k0 + k];
        }
        #pragma unroll
        for (int i = 0; i < 8; i++) {
            int idx = i * 256 + t;
            int n = idx & 63, k = idx >> 6;
            Bs[k][n] = Wo[(size_t)(k0 + k) * Ec + n0 + n];
        }
        __syncthreads();
        #pragma unroll
        for (int kk = 0; kk < 32; kk++) {
            float4 a = *(const float4*)&As[kk][r0];
            float4 b = *(const float4*)&Bs[kk][c0];
            float av[4] = {a.x, a.y, a.z, a.w};
            float bw[4] = {b.x, b.y, b.z, b.w};
            #pragma unroll
            for (int i = 0; i < 4; i++)
                #pragma unroll
                for (int j = 0; j < 4; j++)
                    acc[i][j] += av[i] * bw[j];
        }
        __syncthreads();
    }
    #pragma unroll
    for (int i = 0; i < 4; i++) {
        int m = mBase + r0 + i;
        #pragma unroll
        for (int j = 0; j < 4; j++) {
            int n = n0 + c0 + j;
            out[(size_t)m * Ec + n] = acc[i][j] + bo[n];
        }
    }
}

// ---------------- launch ----------------
extern "C" void kernel_launch(void* const* d_in, const int* in_sizes, int n_in,
                              void* d_out, int out_size)
{
    const float* x  = (const float*)d_in[0];
    const void*  pp = d_in[1];
    const float* Wq = (const float*)d_in[2];
    const float* bq = (const float*)d_in[3];
    const float* Wk = (const float*)d_in[4];
    const float* bk = (const float*)d_in[5];
    const float* Wv = (const float*)d_in[6];
    const float* bv = (const float*)d_in[7];
    const float* Wo = (const float*)d_in[8];
    const float* bo = (const float*)d_in[9];
    float* out = (float*)d_out;

    detect_pad_kernel<<<1, 256>>>((const unsigned int*)pp);
    extract_pad_kernel<<<Mc / 256, 256>>>((const int*)pp);

    qkv_gemm_kernel<<<dim3(24, Mc / 64), 256>>>(x, Wq, bq, Wk, bk, Wv, bv);

    static_assert(ATTN_SMEM_FLOATS * 4 < 228 * 1024, "smem");
    cudaFuncSetAttribute(attn_kernel, cudaFuncAttributeMaxDynamicSharedMemorySize,
                         ATTN_SMEM_FLOATS * sizeof(float));
    attn_kernel<<<dim3(Sc / 64, Bc * Hc), 256, ATTN_SMEM_FLOATS * sizeof(float)>>>();

    out_gemm_kernel<<<dim3(HDc / 64, Mc / 64), 256>>>(Wo, bo, out);
}